// round 6
// baseline (speedup 1.0000x reference)
#include <cuda_runtime.h>

#define NN 128
#define PITCH 132          // rows 16B-aligned -> float4 row ops
#define NB 8               // panel width; 16 block steps
#define THREADS 256
#define SMEM_FLOATS (NN*PITCH + 8*NN)
#define SMEM_BYTES (SMEM_FLOATS * sizeof(float))

// ---- warp-0 register panel factorization (pivot-flag, no swaps) ----
__device__ __forceinline__ void factor_panel(
    float (&pn)[4][NB], unsigned &act,
    float* __restrict__ A, float* __restrict__ spiv,
    int* __restrict__ listb, int* __restrict__ pivrowb,
    int* __restrict__ nactb, const int kbn, const int lane)
{
    const unsigned FULL = 0xFFFFFFFFu;
    #pragma unroll
    for (int kk = 0; kk < NB; ++kk) {
        unsigned key = 0u;
        #pragma unroll
        for (int s2 = 0; s2 < 4; ++s2)
            if ((act >> s2) & 1u) {
                const unsigned kv =
                    (__float_as_uint(fabsf(pn[s2][kk])) & 0xFFFFFF80u)
                    | (unsigned)(lane + 32 * s2);
                key = key > kv ? key : kv;
            }
        const unsigned mm = __reduce_max_sync(FULL, key);
        const int p = (int)(mm & 127u);
        const int plane = p & 31;
        const int pslot = p >> 5;

        float up[NB];
        #pragma unroll
        for (int j = kk; j < NB; ++j) {
            const float t = pslot == 0 ? pn[0][j]
                          : pslot == 1 ? pn[1][j]
                          : pslot == 2 ? pn[2][j] : pn[3][j];
            up[j] = __shfl_sync(FULL, t, plane);
        }
        const float pv = up[kk];
        const float rp_ = __fdividef(1.0f, pv);
        if (lane == plane) act &= ~(1u << pslot);
        if (lane == 0) { pivrowb[kk] = p; spiv[kbn + kk] = pv; }

        #pragma unroll
        for (int s2 = 0; s2 < 4; ++s2)
            if ((act >> s2) & 1u) {
                const float l = pn[s2][kk] * rp_;
                pn[s2][kk] = l;
                #pragma unroll
                for (int j = kk + 1; j < NB; ++j)
                    pn[s2][j] = fmaf(-l, up[j], pn[s2][j]);
            }
    }
    // write back panel (L multipliers + pivot-row U/L mix)
    #pragma unroll
    for (int s2 = 0; s2 < 4; ++s2) {
        float* row = A + (unsigned)(lane + 32 * s2) * PITCH + kbn;
        *(float4*)row =
            make_float4(pn[s2][0], pn[s2][1], pn[s2][2], pn[s2][3]);
        *(float4*)(row + 4) =
            make_float4(pn[s2][4], pn[s2][5], pn[s2][6], pn[s2][7]);
    }
    // ballot-compact active-row list
    int base = 0;
    #pragma unroll
    for (int s2 = 0; s2 < 4; ++s2) {
        const unsigned am = __ballot_sync(FULL, (act >> s2) & 1u);
        const int pos = base + __popc(am & ((1u << lane) - 1u));
        if ((act >> s2) & 1u) listb[pos] = lane + 32 * s2;
        base += __popc(am);
    }
    if (lane == 0) *nactb = base;
}

__global__ void __launch_bounds__(THREADS, 3)
lsd_kernel(const float* __restrict__ rs,
           const float* __restrict__ kp,
           const float* __restrict__ cw,
           const float* __restrict__ sw,
           float* __restrict__ out)
{
    extern __shared__ float smem[];
    float* A   = smem;                 // NN * PITCH
    float* kx  = smem + NN * PITCH;    // build only
    float* ky  = kx + NN;
    float* kz  = ky + NN;
    float* scw = kz + NN;
    float* ssw = scw + NN;
    float* sr  = ssw + NN;             // 3*NN build only
    // aliases after build:
    float* spiv  = kx;                 // NN pivots
    int*   list0 = (int*)ky;           // active lists (double-buffered)
    int*   list1 = (int*)kz;

    __shared__ int s_pivrow[2][NB];
    __shared__ int s_nact[2];
    __shared__ float s_part[4];

    const int tid = threadIdx.x;
    const int b = blockIdx.x;
    const unsigned FULL = 0xFFFFFFFFu;
    const int lane = tid & 31;
    const int wid = tid >> 5;

    if (tid < NN) {
        kx[tid]  = kp[3 * tid + 0];
        ky[tid]  = kp[3 * tid + 1];
        kz[tid]  = kp[3 * tid + 2];
        scw[tid] = cw[tid];
        ssw[tid] = sw[tid];
    }
    const float* rsb = rs + (size_t)b * (3 * NN);
    for (int t = tid; t < 3 * NN; t += THREADS) sr[t] = rsb[t];
    __syncthreads();

    for (int idx = tid; idx < NN * NN; idx += THREADS) {
        const int i = idx >> 7;
        const int m = idx & 127;
        float d = fmaf(sr[3 * i], kx[m],
                  fmaf(sr[3 * i + 1], ky[m], sr[3 * i + 2] * kz[m]));
        float s, c;
        __sincosf(d, &s, &c);
        A[i * PITCH + m] = scw[m] * c - ssw[m] * s;
    }
    __syncthreads();

    unsigned act = 0xFu;   // warp-0 active-row mask (4 slot bits per lane)

    // ---- prologue: factor panel 0 ----
    if (tid < 32) {
        float pn[4][NB];
        #pragma unroll
        for (int s2 = 0; s2 < 4; ++s2) {
            const float* row = A + (unsigned)(lane + 32 * s2) * PITCH;
            const float4 a0 = *(const float4*)row;
            const float4 a1 = *(const float4*)(row + 4);
            pn[s2][0]=a0.x; pn[s2][1]=a0.y; pn[s2][2]=a0.z; pn[s2][3]=a0.w;
            pn[s2][4]=a1.x; pn[s2][5]=a1.y; pn[s2][6]=a1.z; pn[s2][7]=a1.w;
        }
        factor_panel(pn, act, A, spiv, list0, s_pivrow[0], &s_nact[0], 0, lane);
    }
    __syncthreads();

    // ---- main loop with lookahead ----
    for (int kb = 0; kb + NB < NN; kb += NB) {
        const int pb = (kb >> 3) & 1;
        int* listpb = pb ? list1 : list0;
        int* listnb = pb ? list0 : list1;

        if (wid == 0) {
            // === lookahead: update next-panel cols with panel kb, then factor ===
            const int kbn = kb + NB;
            float pn[4][NB];
            float Lb[4][NB];
            #pragma unroll
            for (int s2 = 0; s2 < 4; ++s2) {
                const float* row = A + (unsigned)(lane + 32 * s2) * PITCH;
                const float4 a0 = *(const float4*)(row + kbn);
                const float4 a1 = *(const float4*)(row + kbn + 4);
                pn[s2][0]=a0.x; pn[s2][1]=a0.y; pn[s2][2]=a0.z; pn[s2][3]=a0.w;
                pn[s2][4]=a1.x; pn[s2][5]=a1.y; pn[s2][6]=a1.z; pn[s2][7]=a1.w;
                const float4 l0 = *(const float4*)(row + kb);
                const float4 l1 = *(const float4*)(row + kb + 4);
                Lb[s2][0]=l0.x; Lb[s2][1]=l0.y; Lb[s2][2]=l0.z; Lb[s2][3]=l0.w;
                Lb[s2][4]=l1.x; Lb[s2][5]=l1.y; Lb[s2][6]=l1.z; Lb[s2][7]=l1.w;
            }
            // retire step per slot packed in 4-bit fields (8 = always update)
            unsigned rsp = 0u;
            #pragma unroll
            for (int s2 = 0; s2 < 4; ++s2) {
                const int r = lane + 32 * s2;
                int rsv = ((act >> s2) & 1u) ? 8 : 0;
                #pragma unroll
                for (int m = 0; m < NB; ++m)
                    if (r == s_pivrow[pb][m]) rsv = m;
                rsp |= (unsigned)rsv << (4 * s2);
            }
            // rank-8 update (sequential over pivot rows = implicit TRSM)
            #pragma unroll
            for (int n = 0; n < NB; ++n) {
                const int p = s_pivrow[pb][n];     // uniform LDS
                const int plane = p & 31;
                const int pslot = p >> 5;
                float v[NB];
                #pragma unroll
                for (int j = 0; j < NB; ++j) {
                    const float t = pslot == 0 ? pn[0][j]
                                  : pslot == 1 ? pn[1][j]
                                  : pslot == 2 ? pn[2][j] : pn[3][j];
                    v[j] = __shfl_sync(FULL, t, plane);
                }
                #pragma unroll
                for (int s2 = 0; s2 < 4; ++s2) {
                    if ((int)((rsp >> (4 * s2)) & 15u) > n) {
                        const float l = Lb[s2][n];
                        #pragma unroll
                        for (int j = 0; j < NB; ++j)
                            pn[s2][j] = fmaf(-l, v[j], pn[s2][j]);
                    }
                }
            }
            factor_panel(pn, act, A, spiv, listnb,
                         s_pivrow[pb ^ 1], &s_nact[pb ^ 1], kbn, lane);
        } else {
            // === trailing GEMM for step kb on cols [kb+16, NN) ===
            const int c1 = kb + 2 * NB;
            if (c1 < NN) {
                const int q0v = c1 >> 2;
                const int Q = 32 - q0v;
                const int rp = 32 / Q;             // rows per warp-iter
                const int sub = lane / Q;
                const int qi = lane - sub * Q;
                if (sub < rp) {
                    const int q = q0v + qi;
                    // fused TRSM: build U12 slice for this quad in registers
                    float4 u[NB];
                    #pragma unroll
                    for (int m = 0; m < NB; ++m)
                        u[m] = *(const float4*)(A + s_pivrow[pb][m] * PITCH + 4 * q);
                    #pragma unroll
                    for (int m = 1; m < NB; ++m) {
                        #pragma unroll
                        for (int n = 0; n < m; ++n) {
                            const float l11 =
                                A[s_pivrow[pb][m] * PITCH + kb + n]; // broadcast
                            u[m].x = fmaf(-l11, u[n].x, u[m].x);
                            u[m].y = fmaf(-l11, u[n].y, u[m].y);
                            u[m].z = fmaf(-l11, u[n].z, u[m].z);
                            u[m].w = fmaf(-l11, u[n].w, u[m].w);
                        }
                    }
                    const int nact = s_nact[pb];
                    for (int idx = (wid - 1) * rp + sub; idx < nact; idx += 7 * rp) {
                        float* Arow = A + (unsigned)listpb[idx] * PITCH;
                        const float4 l0 = *(const float4*)(Arow + kb);
                        const float4 l1 = *(const float4*)(Arow + kb + 4);
                        float4 a = *(float4*)(Arow + 4 * q);
                        const float lm[NB] = {l0.x, l0.y, l0.z, l0.w,
                                              l1.x, l1.y, l1.z, l1.w};
                        #pragma unroll
                        for (int m = 0; m < NB; ++m) {
                            a.x = fmaf(-lm[m], u[m].x, a.x);
                            a.y = fmaf(-lm[m], u[m].y, a.y);
                            a.z = fmaf(-lm[m], u[m].z, a.z);
                            a.w = fmaf(-lm[m], u[m].w, a.w);
                        }
                        *(float4*)(Arow + 4 * q) = a;
                    }
                }
            }
        }
        __syncthreads();
    }

    // ---- log|det| = sum log|piv| ----
    float lv = 0.0f;
    if (tid < NN) lv = __logf(fabsf(spiv[tid]));
    #pragma unroll
    for (int o = 16; o > 0; o >>= 1)
        lv += __shfl_xor_sync(FULL, lv, o);
    if (tid < NN && (tid & 31) == 0) s_part[tid >> 5] = lv;
    __syncthreads();
    if (tid == 0)
        out[b] = s_part[0] + s_part[1] + s_part[2] + s_part[3];
}

extern "C" void kernel_launch(void* const* d_in, const int* in_sizes, int n_in,
                              void* d_out, int out_size)
{
    const float* rs = (const float*)d_in[0];
    const float* kp = (const float*)d_in[1];
    const float* cw = (const float*)d_in[2];
    const float* sw = (const float*)d_in[3];
    float* out = (float*)d_out;

    const int batch = in_sizes[0] / (3 * NN);

    cudaFuncSetAttribute(lsd_kernel,
                         cudaFuncAttributeMaxDynamicSharedMemorySize,
                         (int)SMEM_BYTES);

    lsd_kernel<<<batch, THREADS, SMEM_BYTES>>>(rs, kp, cw, sw, out);
}

// round 7
// speedup vs baseline: 1.1671x; 1.1671x over previous
#include <cuda_runtime.h>

#define NN 128
#define PITCH 132          // rows 16B-aligned -> float4 row ops
#define NB 8               // panel width; 16 panels
#define THREADS 256
#define SMEM_FLOATS (NN*PITCH + 8*NN)
#define SMEM_BYTES (SMEM_FLOATS * sizeof(float))

#define BAR_ARRIVE(id) asm volatile("bar.arrive %0, %1;" :: "r"(id), "r"(THREADS) : "memory")
#define BAR_WAIT(id)   asm volatile("bar.sync %0, %1;"   :: "r"(id), "r"(THREADS) : "memory")

// ---- warp-0 register panel factorization (pivot-flag, no swaps) ----
__device__ __forceinline__ void factor_panel(
    float (&pn)[4][NB], unsigned &act,
    float* __restrict__ A, float* __restrict__ spiv,
    int* __restrict__ listb, int* __restrict__ pivrowb,
    int* __restrict__ nactb, const int kbn, const int lane)
{
    const unsigned FULL = 0xFFFFFFFFu;
    #pragma unroll
    for (int kk = 0; kk < NB; ++kk) {
        unsigned key = 0u;
        #pragma unroll
        for (int s2 = 0; s2 < 4; ++s2)
            if ((act >> s2) & 1u) {
                const unsigned kv =
                    (__float_as_uint(fabsf(pn[s2][kk])) & 0xFFFFFF80u)
                    | (unsigned)(lane + 32 * s2);
                key = key > kv ? key : kv;
            }
        const unsigned mm = __reduce_max_sync(FULL, key);
        const int p = (int)(mm & 127u);
        const int plane = p & 31;
        const int pslot = p >> 5;

        float up[NB];
        #pragma unroll
        for (int j = kk; j < NB; ++j) {
            const float t = pslot == 0 ? pn[0][j]
                          : pslot == 1 ? pn[1][j]
                          : pslot == 2 ? pn[2][j] : pn[3][j];
            up[j] = __shfl_sync(FULL, t, plane);
        }
        const float pv = up[kk];
        const float rp_ = __fdividef(1.0f, pv);
        if (lane == plane) act &= ~(1u << pslot);
        if (lane == 0) { pivrowb[kk] = p; spiv[kbn + kk] = pv; }

        #pragma unroll
        for (int s2 = 0; s2 < 4; ++s2)
            if ((act >> s2) & 1u) {
                const float l = pn[s2][kk] * rp_;
                pn[s2][kk] = l;
                #pragma unroll
                for (int j = kk + 1; j < NB; ++j)
                    pn[s2][j] = fmaf(-l, up[j], pn[s2][j]);
            }
    }
    // write back panel (L multipliers + pivot-row values)
    #pragma unroll
    for (int s2 = 0; s2 < 4; ++s2) {
        float* row = A + (unsigned)(lane + 32 * s2) * PITCH + kbn;
        *(float4*)row =
            make_float4(pn[s2][0], pn[s2][1], pn[s2][2], pn[s2][3]);
        *(float4*)(row + 4) =
            make_float4(pn[s2][4], pn[s2][5], pn[s2][6], pn[s2][7]);
    }
    // ballot-compact active-row list
    int base = 0;
    #pragma unroll
    for (int s2 = 0; s2 < 4; ++s2) {
        const unsigned am = __ballot_sync(FULL, (act >> s2) & 1u);
        const int pos = base + __popc(am & ((1u << lane) - 1u));
        if ((act >> s2) & 1u) listb[pos] = lane + 32 * s2;
        base += __popc(am);
    }
    if (lane == 0) *nactb = base;
}

// ---- load U12 quad for column-quad q and apply in-register TRSM ----
__device__ __forceinline__ void load_u_trsm(
    float4 (&u)[NB], const float* __restrict__ A,
    const int* __restrict__ prow, const int kb, const int q)
{
    #pragma unroll
    for (int m = 0; m < NB; ++m)
        u[m] = *(const float4*)(A + prow[m] * PITCH + 4 * q);
    #pragma unroll
    for (int m = 1; m < NB; ++m) {
        #pragma unroll
        for (int n = 0; n < m; ++n) {
            const float l11 = A[prow[m] * PITCH + kb + n];  // uniform -> bcast
            u[m].x = fmaf(-l11, u[n].x, u[m].x);
            u[m].y = fmaf(-l11, u[n].y, u[m].y);
            u[m].z = fmaf(-l11, u[n].z, u[m].z);
            u[m].w = fmaf(-l11, u[n].w, u[m].w);
        }
    }
}

__device__ __forceinline__ void row_update(
    float* __restrict__ Arow, const int kb, const int q, const float4 (&u)[NB])
{
    const float4 l0 = *(const float4*)(Arow + kb);
    const float4 l1 = *(const float4*)(Arow + kb + 4);
    float4 a = *(float4*)(Arow + 4 * q);
    const float lm[NB] = {l0.x, l0.y, l0.z, l0.w, l1.x, l1.y, l1.z, l1.w};
    #pragma unroll
    for (int m = 0; m < NB; ++m) {
        a.x = fmaf(-lm[m], u[m].x, a.x);
        a.y = fmaf(-lm[m], u[m].y, a.y);
        a.z = fmaf(-lm[m], u[m].z, a.z);
        a.w = fmaf(-lm[m], u[m].w, a.w);
    }
    *(float4*)(Arow + 4 * q) = a;
}

__global__ void __launch_bounds__(THREADS, 3)
lsd_kernel(const float* __restrict__ rs,
           const float* __restrict__ kp,
           const float* __restrict__ cw,
           const float* __restrict__ sw,
           float* __restrict__ out)
{
    extern __shared__ float smem[];
    float* A   = smem;                 // NN * PITCH
    float* kx  = smem + NN * PITCH;    // build only
    float* ky  = kx + NN;
    float* kz  = ky + NN;
    float* scw = kz + NN;
    float* ssw = scw + NN;
    float* sr  = ssw + NN;             // 3*NN, build only
    // aliases after build:
    float* spiv  = kx;                 // NN pivots
    int*   list0 = (int*)ky;           // active lists (double-buffered)
    int*   list1 = (int*)kz;

    __shared__ int s_pivrow[2][NB];
    __shared__ int s_nact[2];
    __shared__ float s_part[4];

    const int tid = threadIdx.x;
    const int b = blockIdx.x;
    const unsigned FULL = 0xFFFFFFFFu;
    const int lane = tid & 31;
    const int wid = tid >> 5;

    if (tid < NN) {
        kx[tid]  = kp[3 * tid + 0];
        ky[tid]  = kp[3 * tid + 1];
        kz[tid]  = kp[3 * tid + 2];
        scw[tid] = cw[tid];
        ssw[tid] = sw[tid];
    }
    const float* rsb = rs + (size_t)b * (3 * NN);
    for (int t = tid; t < 3 * NN; t += THREADS) sr[t] = rsb[t];
    __syncthreads();

    // Build Slater matrix: A[i][m] = cw[m]*cos(k_m.r_i) - sw[m]*sin(k_m.r_i)
    for (int idx = tid; idx < NN * NN; idx += THREADS) {
        const int i = idx >> 7;
        const int m = idx & 127;
        float d = fmaf(sr[3 * i], kx[m],
                  fmaf(sr[3 * i + 1], ky[m], sr[3 * i + 2] * kz[m]));
        float s, c;
        __sincosf(d, &s, &c);
        A[i * PITCH + m] = scw[m] * c - ssw[m] * s;
    }
    __syncthreads();

    unsigned act = 0xFu;   // warp-0 active-row mask (slot bits per lane)

    // ---- prologue: factor panel 0 (warp 0, registers) ----
    if (tid < 32) {
        float pn[4][NB];
        #pragma unroll
        for (int s2 = 0; s2 < 4; ++s2) {
            const float* row = A + (unsigned)(lane + 32 * s2) * PITCH;
            const float4 a0 = *(const float4*)row;
            const float4 a1 = *(const float4*)(row + 4);
            pn[s2][0]=a0.x; pn[s2][1]=a0.y; pn[s2][2]=a0.z; pn[s2][3]=a0.w;
            pn[s2][4]=a1.x; pn[s2][5]=a1.y; pn[s2][6]=a1.z; pn[s2][7]=a1.w;
        }
        factor_panel(pn, act, A, spiv, list0, s_pivrow[0], &s_nact[0], 0, lane);
    }
    __syncthreads();

    // ---- pipelined main loop: one __syncthreads per step ----
    for (int kb = 0; kb + NB < NN; kb += NB) {
        const int pb = (kb >> 3) & 1;
        int* listpb = pb ? list1 : list0;
        int* listnb = pb ? list0 : list1;
        const int kbn = kb + NB;

        if (wid == 0) {
            // wait until GEMM warps finish the 2 next-panel quads
            BAR_WAIT(1);
            float pn[4][NB];
            #pragma unroll
            for (int s2 = 0; s2 < 4; ++s2) {
                const float* row = A + (unsigned)(lane + 32 * s2) * PITCH + kbn;
                const float4 a0 = *(const float4*)row;
                const float4 a1 = *(const float4*)(row + 4);
                pn[s2][0]=a0.x; pn[s2][1]=a0.y; pn[s2][2]=a0.z; pn[s2][3]=a0.w;
                pn[s2][4]=a1.x; pn[s2][5]=a1.y; pn[s2][6]=a1.z; pn[s2][7]=a1.w;
            }
            factor_panel(pn, act, A, spiv, listnb,
                         s_pivrow[pb ^ 1], &s_nact[pb ^ 1], kbn, lane);
        } else {
            const int nact = s_nact[pb];
            const int* prow = s_pivrow[pb];

            // --- lookahead: the 2 quads of next panel (cols kbn..kbn+7) ---
            {
                const int q = (kbn >> 2) + (lane & 1);
                float4 u[NB];
                load_u_trsm(u, A, prow, kb, q);
                for (int idx = (wid - 1) * 16 + (lane >> 1); idx < nact; idx += 112)
                    row_update(A + (unsigned)listpb[idx] * PITCH, kb, q, u);
                __threadfence_block();
                BAR_ARRIVE(1);
            }

            // --- main GEMM: cols [kbn+8, NN), overlapped with warp-0 factor ---
            const int c1 = kbn + NB;
            if (c1 < NN) {
                const int q0v = c1 >> 2;
                const int Q = 32 - q0v;
                if (lane < Q) {
                    const int q = q0v + lane;
                    float4 u[NB];
                    load_u_trsm(u, A, prow, kb, q);
                    for (int idx = wid - 1; idx < nact; idx += 7)
                        row_update(A + (unsigned)listpb[idx] * PITCH, kb, q, u);
                }
            }
        }
        __syncthreads();
    }

    // ---- log|det| = sum log|piv| ----
    float lv = 0.0f;
    if (tid < NN) lv = __logf(fabsf(spiv[tid]));
    #pragma unroll
    for (int o = 16; o > 0; o >>= 1)
        lv += __shfl_xor_sync(FULL, lv, o);
    if (tid < NN && (tid & 31) == 0) s_part[tid >> 5] = lv;
    __syncthreads();
    if (tid == 0)
        out[b] = s_part[0] + s_part[1] + s_part[2] + s_part[3];
}

extern "C" void kernel_launch(void* const* d_in, const int* in_sizes, int n_in,
                              void* d_out, int out_size)
{
    const float* rs = (const float*)d_in[0];
    const float* kp = (const float*)d_in[1];
    const float* cw = (const float*)d_in[2];
    const float* sw = (const float*)d_in[3];
    float* out = (float*)d_out;

    const int batch = in_sizes[0] / (3 * NN);

    cudaFuncSetAttribute(lsd_kernel,
                         cudaFuncAttributeMaxDynamicSharedMemorySize,
                         (int)SMEM_BYTES);

    lsd_kernel<<<batch, THREADS, SMEM_BYTES>>>(rs, kp, cw, sw, out);
}

// round 8
// speedup vs baseline: 1.1682x; 1.0009x over previous
#include <cuda_runtime.h>

#define NN 128
#define PITCH 132          // rows 16B-aligned -> float4 row ops
#define NB 8               // panel width; 16 panels
#define THREADS 256
#define SMEM_FLOATS (NN*PITCH + 8*NN)
#define SMEM_BYTES (SMEM_FLOATS * sizeof(float))

#define BAR_ARRIVE(id) asm volatile("bar.arrive %0, %1;" :: "r"(id), "r"(THREADS) : "memory")
#define BAR_WAIT(id)   asm volatile("bar.sync %0, %1;"   :: "r"(id), "r"(THREADS) : "memory")

// ---- warp-0 register panel factorization (pivot-flag, no swaps) ----
__device__ __forceinline__ void factor_panel(
    float (&pn)[4][NB], unsigned &act,
    float* __restrict__ A, float* __restrict__ spiv,
    int* __restrict__ listb, int* __restrict__ pivrowb,
    int* __restrict__ nactb, const int kbn, const int lane)
{
    const unsigned FULL = 0xFFFFFFFFu;
    #pragma unroll
    for (int kk = 0; kk < NB; ++kk) {
        unsigned key = 0u;
        #pragma unroll
        for (int s2 = 0; s2 < 4; ++s2)
            if ((act >> s2) & 1u) {
                const unsigned kv =
                    (__float_as_uint(fabsf(pn[s2][kk])) & 0xFFFFFF80u)
                    | (unsigned)(lane + 32 * s2);
                key = key > kv ? key : kv;
            }
        const unsigned mm = __reduce_max_sync(FULL, key);
        const int p = (int)(mm & 127u);
        const int plane = p & 31;
        const int pslot = p >> 5;

        float up[NB];
        #pragma unroll
        for (int j = kk; j < NB; ++j) {
            const float t = pslot == 0 ? pn[0][j]
                          : pslot == 1 ? pn[1][j]
                          : pslot == 2 ? pn[2][j] : pn[3][j];
            up[j] = __shfl_sync(FULL, t, plane);
        }
        const float pv = up[kk];
        const float rp_ = __fdividef(1.0f, pv);
        if (lane == plane) act &= ~(1u << pslot);
        if (lane == 0) { pivrowb[kk] = p; spiv[kbn + kk] = pv; }

        #pragma unroll
        for (int s2 = 0; s2 < 4; ++s2)
            if ((act >> s2) & 1u) {
                const float l = pn[s2][kk] * rp_;
                pn[s2][kk] = l;
                #pragma unroll
                for (int j = kk + 1; j < NB; ++j)
                    pn[s2][j] = fmaf(-l, up[j], pn[s2][j]);
            }
    }
    // write back panel (L multipliers + pivot-row values)
    #pragma unroll
    for (int s2 = 0; s2 < 4; ++s2) {
        float* row = A + (unsigned)(lane + 32 * s2) * PITCH + kbn;
        *(float4*)row =
            make_float4(pn[s2][0], pn[s2][1], pn[s2][2], pn[s2][3]);
        *(float4*)(row + 4) =
            make_float4(pn[s2][4], pn[s2][5], pn[s2][6], pn[s2][7]);
    }
    // ballot-compact active-row list
    int base = 0;
    #pragma unroll
    for (int s2 = 0; s2 < 4; ++s2) {
        const unsigned am = __ballot_sync(FULL, (act >> s2) & 1u);
        const int pos = base + __popc(am & ((1u << lane) - 1u));
        if ((act >> s2) & 1u) listb[pos] = lane + 32 * s2;
        base += __popc(am);
    }
    if (lane == 0) *nactb = base;
}

// ---- load U12 quad for column-quad q and apply in-register TRSM ----
__device__ __forceinline__ void load_u_trsm(
    float4 (&u)[NB], const float* __restrict__ A,
    const int* __restrict__ prow, const int kb, const int q)
{
    #pragma unroll
    for (int m = 0; m < NB; ++m)
        u[m] = *(const float4*)(A + prow[m] * PITCH + 4 * q);
    #pragma unroll
    for (int m = 1; m < NB; ++m) {
        #pragma unroll
        for (int n = 0; n < m; ++n) {
            const float l11 = A[prow[m] * PITCH + kb + n];  // uniform -> bcast
            u[m].x = fmaf(-l11, u[n].x, u[m].x);
            u[m].y = fmaf(-l11, u[n].y, u[m].y);
            u[m].z = fmaf(-l11, u[n].z, u[m].z);
            u[m].w = fmaf(-l11, u[n].w, u[m].w);
        }
    }
}

__device__ __forceinline__ void row_update(
    float* __restrict__ Arow, const int kb, const int q, const float4 (&u)[NB])
{
    const float4 l0 = *(const float4*)(Arow + kb);
    const float4 l1 = *(const float4*)(Arow + kb + 4);
    float4 a = *(float4*)(Arow + 4 * q);
    const float lm[NB] = {l0.x, l0.y, l0.z, l0.w, l1.x, l1.y, l1.z, l1.w};
    #pragma unroll
    for (int m = 0; m < NB; ++m) {
        a.x = fmaf(-lm[m], u[m].x, a.x);
        a.y = fmaf(-lm[m], u[m].y, a.y);
        a.z = fmaf(-lm[m], u[m].z, a.z);
        a.w = fmaf(-lm[m], u[m].w, a.w);
    }
    *(float4*)(Arow + 4 * q) = a;
}

__global__ void __launch_bounds__(THREADS, 3)
lsd_kernel(const float* __restrict__ rs,
           const float* __restrict__ kp,
           const float* __restrict__ cw,
           const float* __restrict__ sw,
           float* __restrict__ out)
{
    extern __shared__ float smem[];
    float* A   = smem;                 // NN * PITCH
    float* kx  = smem + NN * PITCH;    // build only
    float* ky  = kx + NN;
    float* kz  = ky + NN;
    float* scw = kz + NN;
    float* ssw = scw + NN;
    float* sr  = ssw + NN;             // 3*NN, build only
    // aliases after build:
    float* spiv  = kx;                 // NN pivots
    int*   list0 = (int*)ky;           // active lists (double-buffered)
    int*   list1 = (int*)kz;

    __shared__ int s_pivrow[2][NB];
    __shared__ int s_nact[2];
    __shared__ float s_part[4];

    const int tid = threadIdx.x;
    const int b = blockIdx.x;
    const unsigned FULL = 0xFFFFFFFFu;
    const int lane = tid & 31;
    const int wid = tid >> 5;

    if (tid < NN) {
        kx[tid]  = kp[3 * tid + 0];
        ky[tid]  = kp[3 * tid + 1];
        kz[tid]  = kp[3 * tid + 2];
        scw[tid] = cw[tid];
        ssw[tid] = sw[tid];
    }
    const float* rsb = rs + (size_t)b * (3 * NN);
    for (int t = tid; t < 3 * NN; t += THREADS) sr[t] = rsb[t];
    __syncthreads();

    // Build Slater matrix: A[i][m] = cw[m]*cos(k_m.r_i) - sw[m]*sin(k_m.r_i)
    for (int idx = tid; idx < NN * NN; idx += THREADS) {
        const int i = idx >> 7;
        const int m = idx & 127;
        float d = fmaf(sr[3 * i], kx[m],
                  fmaf(sr[3 * i + 1], ky[m], sr[3 * i + 2] * kz[m]));
        float s, c;
        __sincosf(d, &s, &c);
        A[i * PITCH + m] = scw[m] * c - ssw[m] * s;
    }
    __syncthreads();

    unsigned act = 0xFu;   // warp-0 active-row mask (slot bits per lane)

    // ---- prologue: factor panel 0 (warp 0, registers) ----
    if (tid < 32) {
        float pn[4][NB];
        #pragma unroll
        for (int s2 = 0; s2 < 4; ++s2) {
            const float* row = A + (unsigned)(lane + 32 * s2) * PITCH;
            const float4 a0 = *(const float4*)row;
            const float4 a1 = *(const float4*)(row + 4);
            pn[s2][0]=a0.x; pn[s2][1]=a0.y; pn[s2][2]=a0.z; pn[s2][3]=a0.w;
            pn[s2][4]=a1.x; pn[s2][5]=a1.y; pn[s2][6]=a1.z; pn[s2][7]=a1.w;
        }
        factor_panel(pn, act, A, spiv, list0, s_pivrow[0], &s_nact[0], 0, lane);
    }
    __syncthreads();

    // ---- pipelined main loop: one __syncthreads per step ----
    for (int kb = 0; kb + NB < NN; kb += NB) {
        const int pb = (kb >> 3) & 1;
        int* listpb = pb ? list1 : list0;
        int* listnb = pb ? list0 : list1;
        const int kbn = kb + NB;

        if (wid == 0) {
            // wait until GEMM warps finish the 2 next-panel quads
            BAR_WAIT(1);
            float pn[4][NB];
            #pragma unroll
            for (int s2 = 0; s2 < 4; ++s2) {
                const float* row = A + (unsigned)(lane + 32 * s2) * PITCH + kbn;
                const float4 a0 = *(const float4*)row;
                const float4 a1 = *(const float4*)(row + 4);
                pn[s2][0]=a0.x; pn[s2][1]=a0.y; pn[s2][2]=a0.z; pn[s2][3]=a0.w;
                pn[s2][4]=a1.x; pn[s2][5]=a1.y; pn[s2][6]=a1.z; pn[s2][7]=a1.w;
            }
            factor_panel(pn, act, A, spiv, listnb,
                         s_pivrow[pb ^ 1], &s_nact[pb ^ 1], kbn, lane);
        } else {
            const int nact = s_nact[pb];
            const int* prow = s_pivrow[pb];

            // --- lookahead: the 2 quads of next panel (cols kbn..kbn+7) ---
            {
                const int q = (kbn >> 2) + (lane & 1);
                float4 u[NB];
                load_u_trsm(u, A, prow, kb, q);
                for (int idx = (wid - 1) * 16 + (lane >> 1); idx < nact; idx += 112)
                    row_update(A + (unsigned)listpb[idx] * PITCH, kb, q, u);
                __threadfence_block();
                BAR_ARRIVE(1);
            }

            // --- main GEMM: cols [kbn+8, NN), overlapped with warp-0 factor ---
            const int c1 = kbn + NB;
            if (c1 < NN) {
                const int q0v = c1 >> 2;
                const int Q = 32 - q0v;
                if (lane < Q) {
                    const int q = q0v + lane;
                    float4 u[NB];
                    load_u_trsm(u, A, prow, kb, q);
                    for (int idx = wid - 1; idx < nact; idx += 7)
                        row_update(A + (unsigned)listpb[idx] * PITCH, kb, q, u);
                }
            }
        }
        __syncthreads();
    }

    // ---- log|det| = sum log|piv| ----
    float lv = 0.0f;
    if (tid < NN) lv = __logf(fabsf(spiv[tid]));
    #pragma unroll
    for (int o = 16; o > 0; o >>= 1)
        lv += __shfl_xor_sync(FULL, lv, o);
    if (tid < NN && (tid & 31) == 0) s_part[tid >> 5] = lv;
    __syncthreads();
    if (tid == 0)
        out[b] = s_part[0] + s_part[1] + s_part[2] + s_part[3];
}

extern "C" void kernel_launch(void* const* d_in, const int* in_sizes, int n_in,
                              void* d_out, int out_size)
{
    const float* rs = (const float*)d_in[0];
    const float* kp = (const float*)d_in[1];
    const float* cw = (const float*)d_in[2];
    const float* sw = (const float*)d_in[3];
    float* out = (float*)d_out;

    const int batch = in_sizes[0] / (3 * NN);

    cudaFuncSetAttribute(lsd_kernel,
                         cudaFuncAttributeMaxDynamicSharedMemorySize,
                         (int)SMEM_BYTES);

    lsd_kernel<<<batch, THREADS, SMEM_BYTES>>>(rs, kp, cw, sw, out);
}